// round 1
// baseline (speedup 1.0000x reference)
#include <cuda_runtime.h>
#include <cuda_bf16.h>
#include <math_constants.h>

// Problem dims
#define BB 4
#define LL 4096
#define DM 1024
#define DD 128          // DK == DV == 128

// Scratch for projected q, k, v  (static device arrays: no runtime allocation)
__device__ float q_g[BB * LL * DD];
__device__ float k_g[BB * LL * DD];
__device__ float v_g[BB * LL * DD];

// ---------------------------------------------------------------------------
// Projection GEMM:  O[M=16384, N=128] = X[M, 1024] @ W[1024, 128]
// BM=64, BN=64, BK=16, 16x16 threads, 4x4 per thread.
// blockIdx.z selects which projection (Q/K/V).
// ---------------------------------------------------------------------------
__global__ __launch_bounds__(256)
void proj_kernel(const float* __restrict__ Qx, const float* __restrict__ Kx,
                 const float* __restrict__ Vx, const float* __restrict__ WQ,
                 const float* __restrict__ WK, const float* __restrict__ WV)
{
    __shared__ float As[16][65];   // [k][m], padded: conflict-free scalar reads
    __shared__ float Bs[16][64];   // [k][n], float4 reads

    const float* X;
    const float* W;
    float* O;
    if (blockIdx.z == 0)      { X = Qx; W = WQ; O = q_g; }
    else if (blockIdx.z == 1) { X = Kx; W = WK; O = k_g; }
    else                      { X = Vx; W = WV; O = v_g; }

    const int tx = threadIdx.x;          // 0..15
    const int ty = threadIdx.y;          // 0..15
    const int tid = ty * 16 + tx;

    const int row0 = blockIdx.y * 64;
    const int col0 = blockIdx.x * 64;

    // A loader: each thread loads 4 consecutive k's of one row
    const int ar  = tid >> 2;            // 0..63
    const int ac0 = (tid & 3) * 4;       // 0,4,8,12
    // B loader: each thread loads float4 of one k-row
    const int bk  = tid >> 4;            // 0..15
    const int bc0 = (tid & 15) * 4;      // 0..60

    float acc[4][4] = {};

    for (int kk = 0; kk < DM; kk += 16) {
        float4 a4 = *reinterpret_cast<const float4*>(
            X + (size_t)(row0 + ar) * DM + kk + ac0);
        As[ac0 + 0][ar] = a4.x;
        As[ac0 + 1][ar] = a4.y;
        As[ac0 + 2][ar] = a4.z;
        As[ac0 + 3][ar] = a4.w;

        *reinterpret_cast<float4*>(&Bs[bk][bc0]) =
            *reinterpret_cast<const float4*>(W + (size_t)(kk + bk) * DD + col0 + bc0);

        __syncthreads();

        #pragma unroll
        for (int k = 0; k < 16; k++) {
            const float a0 = As[k][ty * 4 + 0];
            const float a1 = As[k][ty * 4 + 1];
            const float a2 = As[k][ty * 4 + 2];
            const float a3 = As[k][ty * 4 + 3];
            const float4 b4 = *reinterpret_cast<const float4*>(&Bs[k][tx * 4]);
            acc[0][0] += a0 * b4.x; acc[0][1] += a0 * b4.y; acc[0][2] += a0 * b4.z; acc[0][3] += a0 * b4.w;
            acc[1][0] += a1 * b4.x; acc[1][1] += a1 * b4.y; acc[1][2] += a1 * b4.z; acc[1][3] += a1 * b4.w;
            acc[2][0] += a2 * b4.x; acc[2][1] += a2 * b4.y; acc[2][2] += a2 * b4.z; acc[2][3] += a2 * b4.w;
            acc[3][0] += a3 * b4.x; acc[3][1] += a3 * b4.y; acc[3][2] += a3 * b4.z; acc[3][3] += a3 * b4.w;
        }
        __syncthreads();
    }

    #pragma unroll
    for (int i = 0; i < 4; i++) {
        float4 o;
        o.x = acc[i][0]; o.y = acc[i][1]; o.z = acc[i][2]; o.w = acc[i][3];
        *reinterpret_cast<float4*>(
            O + (size_t)(row0 + ty * 4 + i) * DD + col0 + tx * 4) = o;
    }
}

// ---------------------------------------------------------------------------
// Flash attention (fp32, online softmax).
// Block: 256 threads, 128 queries (pair of threads splits D=128 into halves).
// Key tiles of BN=32 staged in shared; broadcast float4 reads.
// Mask applied BEFORE the 1/sqrt(dk) scale (as in the reference; -inf is
// invariant under scaling so the order is numerically identical).
// ---------------------------------------------------------------------------
#define BM 128
#define BN 32

__global__ __launch_bounds__(256, 1)
void attn_kernel(const int* __restrict__ mask, float* __restrict__ out)
{
    __shared__ float ks[BN][DD];
    __shared__ float vs[BN][DD];
    __shared__ int   msk[BN];

    const int tid   = threadIdx.x;
    const int qi    = tid >> 1;        // query within block: 0..127
    const int half  = tid & 1;         // which D-half this thread owns
    const int dbase = half * 64;
    const int b     = blockIdx.y;
    const int row   = blockIdx.x * BM + qi;

    // q row half in registers (16 x float4 = 64 floats)
    const float* qrow = q_g + ((size_t)(b * LL + row)) * DD + dbase;
    float4 qv[16];
    #pragma unroll
    for (int i = 0; i < 16; i++)
        qv[i] = reinterpret_cast<const float4*>(qrow)[i];

    float4 accv[16];
    #pragma unroll
    for (int i = 0; i < 16; i++) accv[i] = make_float4(0.f, 0.f, 0.f, 0.f);

    float m = -CUDART_INF_F;
    float l = 0.f;
    const float scale = 0.08838834764831845f;   // 1/sqrt(128)

    // tile loader coords: each thread loads 4 float4 (16 floats) per array
    const int j0 = tid >> 3;          // 0..31 (key row)
    const int d0 = (tid & 7) * 16;    // 0..112

    for (int kt = 0; kt < LL / BN; kt++) {
        const int kbase = kt * BN;
        {
            const float* kg = k_g + ((size_t)(b * LL + kbase + j0)) * DD + d0;
            const float* vg = v_g + ((size_t)(b * LL + kbase + j0)) * DD + d0;
            float4* ksd = reinterpret_cast<float4*>(&ks[j0][d0]);
            float4* vsd = reinterpret_cast<float4*>(&vs[j0][d0]);
            #pragma unroll
            for (int i = 0; i < 4; i++) {
                ksd[i] = reinterpret_cast<const float4*>(kg)[i];
                vsd[i] = reinterpret_cast<const float4*>(vg)[i];
            }
            if (tid < BN) msk[tid] = mask[b * LL + kbase + tid];
        }
        __syncthreads();

        // scores for this tile
        float s[BN];
        #pragma unroll
        for (int j = 0; j < BN; j++) {
            const float4* kp = reinterpret_cast<const float4*>(&ks[j][dbase]);
            float sum = 0.f;
            #pragma unroll
            for (int dd = 0; dd < 16; dd++) {
                const float4 k4 = kp[dd];
                sum += qv[dd].x * k4.x + qv[dd].y * k4.y
                     + qv[dd].z * k4.z + qv[dd].w * k4.w;
            }
            sum += __shfl_xor_sync(0xffffffffu, sum, 1);   // combine D-halves
            s[j] = msk[j] ? sum * scale : -CUDART_INF_F;
        }

        // online softmax update
        float tm = -CUDART_INF_F;
        #pragma unroll
        for (int j = 0; j < BN; j++) tm = fmaxf(tm, s[j]);
        const float mnew  = fmaxf(m, tm);
        const float msafe = (mnew == -CUDART_INF_F) ? 0.f : mnew;
        const float corr  = __expf(m - msafe);   // m=-inf -> 0 (acc empty)
        m = mnew;

        float lsum = 0.f;
        #pragma unroll
        for (int j = 0; j < BN; j++) {
            const float p = __expf(s[j] - msafe);
            s[j] = p;
            lsum += p;
        }
        l = l * corr + lsum;

        #pragma unroll
        for (int i = 0; i < 16; i++) {
            accv[i].x *= corr; accv[i].y *= corr;
            accv[i].z *= corr; accv[i].w *= corr;
        }

        #pragma unroll
        for (int j = 0; j < BN; j++) {
            const float p = s[j];
            const float4* vp = reinterpret_cast<const float4*>(&vs[j][dbase]);
            #pragma unroll
            for (int dd = 0; dd < 16; dd++) {
                const float4 v4 = vp[dd];
                accv[dd].x += p * v4.x; accv[dd].y += p * v4.y;
                accv[dd].z += p * v4.z; accv[dd].w += p * v4.w;
            }
        }
        __syncthreads();
    }

    const float inv = 1.f / l;
    float* orow = out + ((size_t)(b * LL + row)) * DD + dbase;
    #pragma unroll
    for (int i = 0; i < 16; i++) {
        float4 o;
        o.x = accv[i].x * inv; o.y = accv[i].y * inv;
        o.z = accv[i].z * inv; o.w = accv[i].w * inv;
        reinterpret_cast<float4*>(orow)[i] = o;
    }
}

// ---------------------------------------------------------------------------
// Launch
// ---------------------------------------------------------------------------
extern "C" void kernel_launch(void* const* d_in, const int* in_sizes, int n_in,
                              void* d_out, int out_size)
{
    const float* Q    = (const float*)d_in[0];
    const float* K    = (const float*)d_in[1];
    const float* V    = (const float*)d_in[2];
    const int*   mask = (const int*)  d_in[3];
    const float* WQ   = (const float*)d_in[4];
    const float* WK   = (const float*)d_in[5];
    const float* WV   = (const float*)d_in[6];
    float* out = (float*)d_out;

    dim3 pg(DD / 64, (BB * LL) / 64, 3);   // (2, 256, 3)
    proj_kernel<<<pg, dim3(16, 16)>>>(Q, K, V, WQ, WK, WV);

    dim3 ag(LL / BM, BB);                  // (32, 4)
    attn_kernel<<<ag, 256>>>(mask, out);
}